// round 14
// baseline (speedup 1.0000x reference)
#include <cuda_runtime.h>
#include <cuda_fp16.h>
#include <math.h>
#include <stdint.h>

#define NND 100000
#define NE  1600000
#define D   128
#define MSCALE 16.0f
#define INV_MSCALE (1.0f / 16.0f)

// Scratch (static device globals — no runtime allocation allowed)
__device__ unsigned char g_buf [NND * D];  // layer-1 messages (e4m3, x16, pre-scaled by dis_src)
__device__ unsigned char g2_buf[NND * D];  // layer-2 messages (e4m3, x16, pre-scaled by dis_src)
__device__ __half h_buf [NND * D];         // activations (fp16)
__device__ float dis_buf[NND];
__device__ int   deg_buf[NND];
__device__ int   scan_tmp[NND];
__device__ int   row_ptr[NND + 1];
__device__ int   cursor[NND];
__device__ int   csr_src[NE];
__device__ int   bsum[256];
__device__ __half W2h_buf[D * D];
__device__ __half Wfh_buf[D * 64];   // fused head weight  Wp1@Wp2 (fp16)
__device__ float bF_buf[64];         // fused head bias    bp1@Wp2 + bp2

// ---------------- cp.async helpers ----------------

__device__ __forceinline__ void cp_async16(uint32_t saddr, const void* gaddr, int szbytes) {
    asm volatile("cp.async.cg.shared.global [%0], [%1], 16, %2;"
                 :: "r"(saddr), "l"(gaddr), "r"(szbytes));
}
__device__ __forceinline__ void cp_async_commit_wait() {
    asm volatile("cp.async.commit_group;");
    asm volatile("cp.async.wait_group 0;");
}

// ---------------- fp8 helpers ----------------

__device__ __forceinline__ unsigned short enc_e4m3x2(float lo, float hi) {
    unsigned short u;
    asm("cvt.rn.satfinite.e4m3x2.f32 %0, %1, %2;" : "=h"(u) : "f"(hi), "f"(lo));
    return u;
}
__device__ __forceinline__ __half2 dec_e4m3x2(unsigned short u) {
    uint32_t r;
    asm("cvt.rn.f16x2.e4m3x2 %0, %1;" : "=r"(r) : "h"(u));
    return *(__half2*)&r;
}

// ---------------- degree / normalization / CSR build ----------------

__global__ void k_count_deg(const int* __restrict__ dst) {
    int t = blockIdx.x * blockDim.x + threadIdx.x;
    if (t * 4 >= NE) return;
    int4 d = *(const int4*)(dst + t * 4);
    atomicAdd(&deg_buf[d.x], 1);
    atomicAdd(&deg_buf[d.y], 1);
    atomicAdd(&deg_buf[d.z], 1);
    atomicAdd(&deg_buf[d.w], 1);
}

#define SCB 512
#define SCAN_BLOCKS ((NND + SCB - 1) / SCB)   // 196

// block-local inclusive scan of deg; also writes dis = rsqrt(deg+1)
__global__ __launch_bounds__(SCB) void k_scan1() {
    __shared__ int sm[SCB];
    int i = blockIdx.x * SCB + threadIdx.x;
    int v = (i < NND) ? deg_buf[i] : 0;
    sm[threadIdx.x] = v;
    if (i < NND) dis_buf[i] = rsqrtf((float)(v + 1));
    __syncthreads();
#pragma unroll
    for (int off = 1; off < SCB; off <<= 1) {
        int t = (threadIdx.x >= off) ? sm[threadIdx.x - off] : 0;
        __syncthreads();
        sm[threadIdx.x] += t;
        __syncthreads();
    }
    if (i < NND) scan_tmp[i] = sm[threadIdx.x];
    if (threadIdx.x == SCB - 1) bsum[blockIdx.x] = sm[SCB - 1];
}

// per-block offset computed in-block from raw bsum[] (replaces scan2)
__global__ __launch_bounds__(SCB) void k_scan3() {
    __shared__ int wsum[SCB / 32];
    __shared__ int blk_off;
    int t    = threadIdx.x;
    int lane = t & 31;
    int v = (t < blockIdx.x && t < SCAN_BLOCKS) ? bsum[t] : 0;
#pragma unroll
    for (int o = 16; o; o >>= 1) v += __shfl_xor_sync(0xFFFFFFFFu, v, o);
    if (lane == 0) wsum[t >> 5] = v;
    __syncthreads();
    if (t == 0) {
        int s = 0;
#pragma unroll
        for (int w = 0; w < SCB / 32; w++) s += wsum[w];
        blk_off = s;
    }
    __syncthreads();
    int i = blockIdx.x * SCB + t;
    if (i >= NND) return;
    int dg  = deg_buf[i];
    int inc = scan_tmp[i] + blk_off;
    int st  = inc - dg;
    row_ptr[i] = st;
    cursor[i]  = st;
    if (i == NND - 1) row_ptr[NND] = inc;
}

__global__ void k_fill(const int* __restrict__ src, const int* __restrict__ dst) {
    int t = blockIdx.x * blockDim.x + threadIdx.x;
    if (t * 4 >= NE) return;
    int4 s = *(const int4*)(src + t * 4);
    int4 d = *(const int4*)(dst + t * 4);
    csr_src[atomicAdd(&cursor[d.x], 1)] = s.x;
    csr_src[atomicAdd(&cursor[d.y], 1)] = s.y;
    csr_src[atomicAdd(&cursor[d.z], 1)] = s.z;
    csr_src[atomicAdd(&cursor[d.w], 1)] = s.w;
}

// ---------------- weight prep: W2->fp16 + fused head weight/bias ----------------

__global__ __launch_bounds__(256) void k_wprep(const float* __restrict__ W2,
                                               const float* __restrict__ Wp1,
                                               const float* __restrict__ bp1,
                                               const float* __restrict__ Wp2,
                                               const float* __restrict__ bp2)
{
    int i = blockIdx.x * blockDim.x + threadIdx.x;
    if (i < D * D) {
        W2h_buf[i] = __float2half_rn(W2[i]);
        return;
    }
    int j = i - D * D;
    if (j >= D * 64) return;
    int k = j >> 6, n = j & 63;
    float s = 0.0f;
#pragma unroll 8
    for (int t = 0; t < D; t++)
        s = fmaf(Wp1[k * D + t], Wp2[t * 64 + n], s);
    Wfh_buf[j] = __float2half_rn(s);
    if (k == 0) {
        float b = bp2[n];
#pragma unroll 8
        for (int t = 0; t < D; t++)
            b = fmaf(bp1[t], Wp2[t * 64 + n], b);
        bF_buf[n] = b;
    }
}

// ---------------- HMMA GEMM (full-K resident): C = A[128rows,128] @ W[128,BN] --------
// 256 threads = 8 warps; warp w owns rows [w*16, w*16+16); mma.sync m16n8k16 fp16->fp32.
// EPI 0: Cq = e4m3(acc * dis[row] * MSCALE)  (fp8 message write)
// EPI 2: Cf = log_softmax(acc + biasC) over row (BN=64)

template <int BN, bool A_HALF, bool W_HALF, int EPI>
__global__ __launch_bounds__(256)
void hgemm(const void* __restrict__ Ain,
           const void* __restrict__ Win,
           const float* __restrict__ biasC,
           const float* __restrict__ dis,
           unsigned char* __restrict__ Cq,
           float* __restrict__ Cf)
{
    constexpr int SAH = D + 8;
    constexpr int SBH = BN + 8;
    constexpr int NT  = BN / 8;
    extern __shared__ __align__(16) __half smem[];
    __half* As = smem;
    __half* Ws = smem + 128 * SAH;

    const int tid  = threadIdx.x;
    const int wid  = tid >> 5;
    const int lane = tid & 31;
    const int row0 = blockIdx.x * 128;
    const int wr0  = wid * 16;

    const uint32_t as_base = (uint32_t)__cvta_generic_to_shared(As);
    const uint32_t ws_base = (uint32_t)__cvta_generic_to_shared(Ws);

    // ---- stage A ----
    if (A_HALF) {
        const __half* Ah = (const __half*)Ain;
#pragma unroll
        for (int p = 0; p < 8; p++) {
            int i  = tid + p * 256;
            int r  = i >> 4, c8 = i & 15;
            int row = row0 + r;
            uint32_t saddr = as_base + (r * SAH + c8 * 8) * 2;
            const __half* gaddr = Ah + (row < NND ? row : 0) * D + c8 * 8;
            cp_async16(saddr, gaddr, row < NND ? 16 : 0);
        }
    } else {
        const float* Af = (const float*)Ain;
#pragma unroll
        for (int p = 0; p < 16; p++) {
            int i  = tid + p * 256;
            int r  = i >> 5, c4 = i & 31;
            int row = row0 + r;
            float4 v = make_float4(0.f, 0.f, 0.f, 0.f);
            if (row < NND)
                v = *(const float4*)(Af + row * D + c4 * 4);
            __half2 h01 = __floats2half2_rn(v.x, v.y);
            __half2 h23 = __floats2half2_rn(v.z, v.w);
            uint2 u;
            u.x = *(uint32_t*)&h01;
            u.y = *(uint32_t*)&h23;
            *(uint2*)(As + r * SAH + c4 * 4) = u;
        }
    }
    // ---- stage W ----
    if (W_HALF) {
        const __half* Wh = (const __half*)Win;
#pragma unroll
        for (int p = 0; p < (D * BN / 8) / 256; p++) {
            int i = tid + p * 256;
            int r = i / (BN / 8), c8 = i % (BN / 8);
            cp_async16(ws_base + (r * SBH + c8 * 8) * 2, Wh + r * BN + c8 * 8, 16);
        }
        cp_async_commit_wait();
    } else {
        const float* Wf = (const float*)Win;
#pragma unroll
        for (int p = 0; p < (D * BN / 4) / 256; p++) {
            int i = tid + p * 256;
            int r = i / (BN / 4), c4 = i % (BN / 4);
            float4 v = *(const float4*)(Wf + r * BN + c4 * 4);
            __half2 h01 = __floats2half2_rn(v.x, v.y);
            __half2 h23 = __floats2half2_rn(v.z, v.w);
            uint2 u;
            u.x = *(uint32_t*)&h01;
            u.y = *(uint32_t*)&h23;
            *(uint2*)(Ws + r * SBH + c4 * 4) = u;
        }
        if (A_HALF) cp_async_commit_wait();
    }
    __syncthreads();

    float c[NT][4];
#pragma unroll
    for (int j = 0; j < NT; j++)
#pragma unroll
        for (int q = 0; q < 4; q++) c[j][q] = 0.0f;

    const uint32_t a_lane = ((wr0 + (lane & 15)) * SAH + (lane >> 4) * 8) * 2;
    const uint32_t b_lane_row = (lane & 15);
    const uint32_t b_lane_col = ((lane & 16) >> 1);

#pragma unroll
    for (int kk = 0; kk < D; kk += 16) {
        uint32_t a0, a1, a2, a3;
        uint32_t aaddr = as_base + a_lane + kk * 2;
        asm volatile("ldmatrix.sync.aligned.m8n8.x4.shared.b16 {%0,%1,%2,%3}, [%4];"
                     : "=r"(a0), "=r"(a1), "=r"(a2), "=r"(a3) : "r"(aaddr));
#pragma unroll
        for (int jt = 0; jt < NT / 2; jt++) {
            uint32_t b0, b1, b2, b3;
            uint32_t baddr = ws_base +
                ((kk + b_lane_row) * SBH + jt * 16 + b_lane_col) * 2;
            asm volatile("ldmatrix.sync.aligned.m8n8.x4.trans.shared.b16 {%0,%1,%2,%3}, [%4];"
                         : "=r"(b0), "=r"(b1), "=r"(b2), "=r"(b3) : "r"(baddr));
            asm volatile("mma.sync.aligned.m16n8k16.row.col.f32.f16.f16.f32 "
                         "{%0,%1,%2,%3},{%4,%5,%6,%7},{%8,%9},{%0,%1,%2,%3};"
                         : "+f"(c[2*jt][0]), "+f"(c[2*jt][1]),
                           "+f"(c[2*jt][2]), "+f"(c[2*jt][3])
                         : "r"(a0), "r"(a1), "r"(a2), "r"(a3), "r"(b0), "r"(b1));
            asm volatile("mma.sync.aligned.m16n8k16.row.col.f32.f16.f16.f32 "
                         "{%0,%1,%2,%3},{%4,%5,%6,%7},{%8,%9},{%0,%1,%2,%3};"
                         : "+f"(c[2*jt+1][0]), "+f"(c[2*jt+1][1]),
                           "+f"(c[2*jt+1][2]), "+f"(c[2*jt+1][3])
                         : "r"(a0), "r"(a1), "r"(a2), "r"(a3), "r"(b2), "r"(b3));
        }
    }

    const int r1 = row0 + wr0 + (lane >> 2);
    const int r2 = r1 + 8;

    if (EPI == 0) {
        float s1 = (r1 < NND) ? dis[r1] * MSCALE : 0.f;
        float s2 = (r2 < NND) ? dis[r2] * MSCALE : 0.f;
#pragma unroll
        for (int j = 0; j < NT; j++) {
            int col = j * 8 + (lane & 3) * 2;
            if (r1 < NND)
                *(unsigned short*)(Cq + r1 * BN + col) =
                    enc_e4m3x2(c[j][0] * s1, c[j][1] * s1);
            if (r2 < NND)
                *(unsigned short*)(Cq + r2 * BN + col) =
                    enc_e4m3x2(c[j][2] * s2, c[j][3] * s2);
        }
    } else {  // EPI 2: BN=64, NT=8, log_softmax per row
        float t[NT][4];
        float m1 = -1e30f, m2 = -1e30f;
#pragma unroll
        for (int j = 0; j < NT; j++) {
            float2 b = *(const float2*)(biasC + j * 8 + (lane & 3) * 2);
            t[j][0] = c[j][0] + b.x; t[j][1] = c[j][1] + b.y;
            t[j][2] = c[j][2] + b.x; t[j][3] = c[j][3] + b.y;
            m1 = fmaxf(m1, fmaxf(t[j][0], t[j][1]));
            m2 = fmaxf(m2, fmaxf(t[j][2], t[j][3]));
        }
#pragma unroll
        for (int o = 1; o <= 2; o <<= 1) {
            m1 = fmaxf(m1, __shfl_xor_sync(0xFFFFFFFFu, m1, o));
            m2 = fmaxf(m2, __shfl_xor_sync(0xFFFFFFFFu, m2, o));
        }
        float s1 = 0.f, s2 = 0.f;
#pragma unroll
        for (int j = 0; j < NT; j++) {
            s1 += expf(t[j][0] - m1) + expf(t[j][1] - m1);
            s2 += expf(t[j][2] - m2) + expf(t[j][3] - m2);
        }
#pragma unroll
        for (int o = 1; o <= 2; o <<= 1) {
            s1 += __shfl_xor_sync(0xFFFFFFFFu, s1, o);
            s2 += __shfl_xor_sync(0xFFFFFFFFu, s2, o);
        }
        float l1 = m1 + logf(s1);
        float l2 = m2 + logf(s2);
#pragma unroll
        for (int j = 0; j < NT; j++) {
            int col = j * 8 + (lane & 3) * 2;
            if (r1 < NND) {
                float2 r; r.x = t[j][0] - l1; r.y = t[j][1] - l1;
                *(float2*)(Cf + r1 * BN + col) = r;
            }
            if (r2 < NND) {
                float2 r; r.x = t[j][2] - l2; r.y = t[j][3] - l2;
                *(float2*)(Cf + r2 * BN + col) = r;
            }
        }
    }
}

// ---------------- CSR gather (fp8 pre-scaled messages, fp16 accum) + finalize -------
// int4 index loads + 16-deep row-load batches (MLP=16).
// h[v] = half(relu(dis[v]/16 * acc + bias))

__device__ __forceinline__ void acc_u32(__half2& a0, __half2& a1, uint32_t u) {
    a0 = __hadd2(a0, dec_e4m3x2((unsigned short)u));
    a1 = __hadd2(a1, dec_e4m3x2((unsigned short)(u >> 16)));
}

__global__ __launch_bounds__(256)
void k_gather_fin(const unsigned char* __restrict__ g, const float* __restrict__ dis,
                  const float* __restrict__ bias, __half* __restrict__ h)
{
    int node = (blockIdx.x * blockDim.x + threadIdx.x) >> 5;
    int lane = threadIdx.x & 31;
    if (node >= NND) return;
    int beg = row_ptr[node];
    int end = row_ptr[node + 1];
    const uint32_t* gp = (const uint32_t*)g;   // 4 fp8 per lane

    __half2 acc0 = __float2half2_rn(0.f);
    __half2 acc1 = __float2half2_rn(0.f);
    acc_u32(acc0, acc1, gp[node * 32 + lane]);   // self-loop message

    int e = beg;
    // peel to 16B-aligned index reads
    while (e < end && (e & 3)) {
        acc_u32(acc0, acc1, gp[__ldg(&csr_src[e]) * 32 + lane]);
        e++;
    }
    // 16-edge batches
    for (; e + 16 <= end; e += 16) {
        int4 i0 = *(const int4*)(csr_src + e);
        int4 i1 = *(const int4*)(csr_src + e + 4);
        int4 i2 = *(const int4*)(csr_src + e + 8);
        int4 i3 = *(const int4*)(csr_src + e + 12);
        uint32_t u0 = gp[i0.x * 32 + lane], u1 = gp[i0.y * 32 + lane];
        uint32_t u2 = gp[i0.z * 32 + lane], u3 = gp[i0.w * 32 + lane];
        uint32_t u4 = gp[i1.x * 32 + lane], u5 = gp[i1.y * 32 + lane];
        uint32_t u6 = gp[i1.z * 32 + lane], u7 = gp[i1.w * 32 + lane];
        uint32_t u8 = gp[i2.x * 32 + lane], u9 = gp[i2.y * 32 + lane];
        uint32_t uA = gp[i2.z * 32 + lane], uB = gp[i2.w * 32 + lane];
        uint32_t uC = gp[i3.x * 32 + lane], uD = gp[i3.y * 32 + lane];
        uint32_t uE = gp[i3.z * 32 + lane], uF = gp[i3.w * 32 + lane];
        acc_u32(acc0, acc1, u0); acc_u32(acc0, acc1, u1);
        acc_u32(acc0, acc1, u2); acc_u32(acc0, acc1, u3);
        acc_u32(acc0, acc1, u4); acc_u32(acc0, acc1, u5);
        acc_u32(acc0, acc1, u6); acc_u32(acc0, acc1, u7);
        acc_u32(acc0, acc1, u8); acc_u32(acc0, acc1, u9);
        acc_u32(acc0, acc1, uA); acc_u32(acc0, acc1, uB);
        acc_u32(acc0, acc1, uC); acc_u32(acc0, acc1, uD);
        acc_u32(acc0, acc1, uE); acc_u32(acc0, acc1, uF);
    }
    // 4-edge batches
    for (; e + 4 <= end; e += 4) {
        int4 i0 = *(const int4*)(csr_src + e);
        uint32_t u0 = gp[i0.x * 32 + lane], u1 = gp[i0.y * 32 + lane];
        uint32_t u2 = gp[i0.z * 32 + lane], u3 = gp[i0.w * 32 + lane];
        acc_u32(acc0, acc1, u0); acc_u32(acc0, acc1, u1);
        acc_u32(acc0, acc1, u2); acc_u32(acc0, acc1, u3);
    }
    for (; e < end; e++)
        acc_u32(acc0, acc1, gp[__ldg(&csr_src[e]) * 32 + lane]);

    float sc = dis[node] * INV_MSCALE;
    float2 f0 = __half22float2(acc0);
    float2 f1 = __half22float2(acc1);
    float4 b = ((const float4*)bias)[lane];
    __half2 r0 = __floats2half2_rn(fmaxf(fmaf(f0.x, sc, b.x), 0.f),
                                   fmaxf(fmaf(f0.y, sc, b.y), 0.f));
    __half2 r1 = __floats2half2_rn(fmaxf(fmaf(f1.x, sc, b.z), 0.f),
                                   fmaxf(fmaf(f1.y, sc, b.w), 0.f));
    uint2 u;
    u.x = *(uint32_t*)&r0;
    u.y = *(uint32_t*)&r1;
    ((uint2*)h)[node * 32 + lane] = u;
}

// ---------------- launch ----------------

extern "C" void kernel_launch(void* const* d_in, const int* in_sizes, int n_in,
                              void* d_out, int out_size)
{
    const float* x   = (const float*)d_in[0];
    const int*   ei  = (const int*)d_in[1];
    const int*   src = ei;
    const int*   dst = ei + NE;
    const float* W1  = (const float*)d_in[2];
    const float* b1  = (const float*)d_in[3];
    const float* W2  = (const float*)d_in[4];
    const float* b2  = (const float*)d_in[5];
    const float* Wp1 = (const float*)d_in[6];
    const float* bp1 = (const float*)d_in[7];
    const float* Wp2 = (const float*)d_in[8];
    const float* bp2 = (const float*)d_in[9];
    float* out = (float*)d_out;

    unsigned char *g_p, *g2_p;
    __half *h_p, *w2h_p, *wfh_p;
    float *dis_p, *bf_p;
    int *deg_p;
    cudaGetSymbolAddress((void**)&g_p,   g_buf);
    cudaGetSymbolAddress((void**)&g2_p,  g2_buf);
    cudaGetSymbolAddress((void**)&h_p,   h_buf);
    cudaGetSymbolAddress((void**)&dis_p, dis_buf);
    cudaGetSymbolAddress((void**)&w2h_p, W2h_buf);
    cudaGetSymbolAddress((void**)&wfh_p, Wfh_buf);
    cudaGetSymbolAddress((void**)&bf_p,  bF_buf);
    cudaGetSymbolAddress((void**)&deg_p, deg_buf);

    const int SM_BN128 = (128 * (D + 8) + D * (128 + 8)) * 2;  // 69632
    const int SM_BN64  = (128 * (D + 8) + D * (64 + 8))  * 2;  // 53248

    static cudaStream_t s2 = nullptr;
    static cudaEvent_t ev_fork, ev_dis, ev_csr, ev_w;
    if (!s2) {
        cudaStreamCreateWithFlags(&s2, cudaStreamNonBlocking);
        cudaEventCreateWithFlags(&ev_fork, cudaEventDisableTiming);
        cudaEventCreateWithFlags(&ev_dis,  cudaEventDisableTiming);
        cudaEventCreateWithFlags(&ev_csr,  cudaEventDisableTiming);
        cudaEventCreateWithFlags(&ev_w,    cudaEventDisableTiming);
        cudaFuncSetAttribute((const void*)hgemm<128, false, false, 0>,
                             cudaFuncAttributeMaxDynamicSharedMemorySize, SM_BN128);
        cudaFuncSetAttribute((const void*)hgemm<128, true, true, 0>,
                             cudaFuncAttributeMaxDynamicSharedMemorySize, SM_BN128);
        cudaFuncSetAttribute((const void*)hgemm<64, true, true, 2>,
                             cudaFuncAttributeMaxDynamicSharedMemorySize, SM_BN64);
    }

    const int GEMM_BLOCKS   = (NND + 127) / 128;       // 782
    const int GATHER_BLOCKS = (NND * 32 + 255) / 256;  // 12500
    const int EDGE4_BLOCKS  = (NE / 4 + 255) / 256;    // 1563

    // ---- fork: CSR build first on s2 (critical), then weight prep ----
    cudaEventRecord(ev_fork, 0);
    cudaStreamWaitEvent(s2, ev_fork, 0);

    cudaMemsetAsync(deg_p, 0, NND * sizeof(int), s2);
    k_count_deg<<<EDGE4_BLOCKS, 256, 0, s2>>>(dst);
    k_scan1<<<SCAN_BLOCKS, SCB, 0, s2>>>();     // also writes dis
    cudaEventRecord(ev_dis, s2);
    k_scan3<<<SCAN_BLOCKS, SCB, 0, s2>>>();     // self-computed block offsets
    k_fill<<<EDGE4_BLOCKS, 256, 0, s2>>>(src, dst);
    cudaEventRecord(ev_csr, s2);
    k_wprep<<<(D * D + D * 64 + 255) / 256, 256, 0, s2>>>(W2, Wp1, bp1, Wp2, bp2);
    cudaEventRecord(ev_w, s2);

    // main: GEMM1 (fp32 A + fp32 W converted in-staging): g = e4m3((x@W1)*dis*16)
    cudaStreamWaitEvent(0, ev_dis, 0);
    hgemm<128, false, false, 0><<<GEMM_BLOCKS, 256, SM_BN128>>>(
        x, W1, nullptr, dis_p, g_p, nullptr);

    cudaStreamWaitEvent(0, ev_csr, 0);

    // ---- layer 1 aggregate: h = half(relu(dis/16*gather(g) + b1)) ----
    k_gather_fin<<<GATHER_BLOCKS, 256>>>(g_p, dis_p, b1, h_p);

    cudaStreamWaitEvent(0, ev_w, 0);

    // ---- layer 2: g2 = e4m3((h@W2)*dis*16) ; h = half(relu(dis/16*gather(g2) + b2)) ----
    hgemm<128, true, true, 0><<<GEMM_BLOCKS, 256, SM_BN128>>>(
        h_p, w2h_p, nullptr, dis_p, g2_p, nullptr);
    k_gather_fin<<<GATHER_BLOCKS, 256>>>(g2_p, dis_p, b2, h_p);

    // ---- fused head + log_softmax: out = logsoftmax(h @ Wf + bF) ----
    hgemm<64, true, true, 2><<<GEMM_BLOCKS, 256, SM_BN64>>>(
        h_p, wfh_p, bf_p, dis_p, nullptr, out);
}

// round 15
// speedup vs baseline: 1.2674x; 1.2674x over previous
#include <cuda_runtime.h>
#include <cuda_fp16.h>
#include <math.h>
#include <stdint.h>

#define NND 100000
#define NE  1600000
#define D   128
#define MSCALE 16.0f
#define INV_MSCALE (1.0f / 16.0f)

// Scratch (static device globals — no runtime allocation allowed)
__device__ unsigned char g_buf [NND * D];  // layer-1 messages (e4m3, x16, pre-scaled by dis_src)
__device__ unsigned char g2_buf[NND * D];  // layer-2 messages (e4m3, x16, pre-scaled by dis_src)
__device__ __half h_buf [NND * D];         // activations (fp16)
__device__ float dis_buf[NND];
__device__ int   deg_buf[NND];
__device__ int   scan_tmp[NND];
__device__ int   row_ptr[NND + 1];
__device__ int   cursor[NND];
__device__ int   csr_src[NE];
__device__ int   bsum[256];
__device__ __half W2h_buf[D * D];
__device__ __half Wfh_buf[D * 64];   // fused head weight  Wp1@Wp2 (fp16)
__device__ float bF_buf[64];         // fused head bias    bp1@Wp2 + bp2

// ---------------- cp.async helpers ----------------

__device__ __forceinline__ void cp_async16(uint32_t saddr, const void* gaddr, int szbytes) {
    asm volatile("cp.async.cg.shared.global [%0], [%1], 16, %2;"
                 :: "r"(saddr), "l"(gaddr), "r"(szbytes));
}
__device__ __forceinline__ void cp_async_commit_wait() {
    asm volatile("cp.async.commit_group;");
    asm volatile("cp.async.wait_group 0;");
}

// ---------------- fp8 helpers ----------------

__device__ __forceinline__ unsigned short enc_e4m3x2(float lo, float hi) {
    unsigned short u;
    asm("cvt.rn.satfinite.e4m3x2.f32 %0, %1, %2;" : "=h"(u) : "f"(hi), "f"(lo));
    return u;
}
__device__ __forceinline__ __half2 dec_e4m3x2(unsigned short u) {
    uint32_t r;
    asm("cvt.rn.f16x2.e4m3x2 %0, %1;" : "=r"(r) : "h"(u));
    return *(__half2*)&r;
}

// ---------------- degree / normalization / CSR build ----------------

__global__ void k_count_deg(const int* __restrict__ dst) {
    int t = blockIdx.x * blockDim.x + threadIdx.x;
    if (t * 4 >= NE) return;
    int4 d = *(const int4*)(dst + t * 4);
    atomicAdd(&deg_buf[d.x], 1);
    atomicAdd(&deg_buf[d.y], 1);
    atomicAdd(&deg_buf[d.z], 1);
    atomicAdd(&deg_buf[d.w], 1);
}

#define SCB 512
#define SCAN_BLOCKS ((NND + SCB - 1) / SCB)   // 196

// block-local inclusive scan of deg; also writes dis = rsqrt(deg+1)
__global__ __launch_bounds__(SCB) void k_scan1() {
    __shared__ int sm[SCB];
    int i = blockIdx.x * SCB + threadIdx.x;
    int v = (i < NND) ? deg_buf[i] : 0;
    sm[threadIdx.x] = v;
    if (i < NND) dis_buf[i] = rsqrtf((float)(v + 1));
    __syncthreads();
#pragma unroll
    for (int off = 1; off < SCB; off <<= 1) {
        int t = (threadIdx.x >= off) ? sm[threadIdx.x - off] : 0;
        __syncthreads();
        sm[threadIdx.x] += t;
        __syncthreads();
    }
    if (i < NND) scan_tmp[i] = sm[threadIdx.x];
    if (threadIdx.x == SCB - 1) bsum[blockIdx.x] = sm[SCB - 1];
}

// per-block offset computed in-block from raw bsum[] (replaces scan2)
__global__ __launch_bounds__(SCB) void k_scan3() {
    __shared__ int wsum[SCB / 32];
    __shared__ int blk_off;
    int t    = threadIdx.x;
    int lane = t & 31;
    int v = (t < blockIdx.x && t < SCAN_BLOCKS) ? bsum[t] : 0;
#pragma unroll
    for (int o = 16; o; o >>= 1) v += __shfl_xor_sync(0xFFFFFFFFu, v, o);
    if (lane == 0) wsum[t >> 5] = v;
    __syncthreads();
    if (t == 0) {
        int s = 0;
#pragma unroll
        for (int w = 0; w < SCB / 32; w++) s += wsum[w];
        blk_off = s;
    }
    __syncthreads();
    int i = blockIdx.x * SCB + t;
    if (i >= NND) return;
    int dg  = deg_buf[i];
    int inc = scan_tmp[i] + blk_off;
    int st  = inc - dg;
    row_ptr[i] = st;
    cursor[i]  = st;
    if (i == NND - 1) row_ptr[NND] = inc;
}

__global__ void k_fill(const int* __restrict__ src, const int* __restrict__ dst) {
    int t = blockIdx.x * blockDim.x + threadIdx.x;
    if (t * 4 >= NE) return;
    int4 s = *(const int4*)(src + t * 4);
    int4 d = *(const int4*)(dst + t * 4);
    csr_src[atomicAdd(&cursor[d.x], 1)] = s.x;
    csr_src[atomicAdd(&cursor[d.y], 1)] = s.y;
    csr_src[atomicAdd(&cursor[d.z], 1)] = s.z;
    csr_src[atomicAdd(&cursor[d.w], 1)] = s.w;
}

// ---------------- weight prep: W2->fp16 + fused head weight/bias ----------------

__global__ __launch_bounds__(256) void k_wprep(const float* __restrict__ W2,
                                               const float* __restrict__ Wp1,
                                               const float* __restrict__ bp1,
                                               const float* __restrict__ Wp2,
                                               const float* __restrict__ bp2)
{
    int i = blockIdx.x * blockDim.x + threadIdx.x;
    if (i < D * D) {
        W2h_buf[i] = __float2half_rn(W2[i]);
        return;
    }
    int j = i - D * D;
    if (j >= D * 64) return;
    int k = j >> 6, n = j & 63;
    float s = 0.0f;
#pragma unroll 8
    for (int t = 0; t < D; t++)
        s = fmaf(Wp1[k * D + t], Wp2[t * 64 + n], s);
    Wfh_buf[j] = __float2half_rn(s);
    if (k == 0) {
        float b = bp2[n];
#pragma unroll 8
        for (int t = 0; t < D; t++)
            b = fmaf(bp1[t], Wp2[t * 64 + n], b);
        bF_buf[n] = b;
    }
}

// ---------------- HMMA GEMM (full-K resident): C = A[128rows,128] @ W[128,BN] --------
// 256 threads = 8 warps; warp w owns rows [w*16, w*16+16); mma.sync m16n8k16 fp16->fp32.
// EPI 0: Cq = e4m3(acc * dis[row] * MSCALE)  (fp8 message write)
// EPI 2: Cf = log_softmax(acc + biasC) over row (BN=64)

template <int BN, bool A_HALF, bool W_HALF, int EPI>
__global__ __launch_bounds__(256)
void hgemm(const void* __restrict__ Ain,
           const void* __restrict__ Win,
           const float* __restrict__ biasC,
           const float* __restrict__ dis,
           unsigned char* __restrict__ Cq,
           float* __restrict__ Cf)
{
    constexpr int SAH = D + 8;
    constexpr int SBH = BN + 8;
    constexpr int NT  = BN / 8;
    extern __shared__ __align__(16) __half smem[];
    __half* As = smem;
    __half* Ws = smem + 128 * SAH;

    const int tid  = threadIdx.x;
    const int wid  = tid >> 5;
    const int lane = tid & 31;
    const int row0 = blockIdx.x * 128;
    const int wr0  = wid * 16;

    const uint32_t as_base = (uint32_t)__cvta_generic_to_shared(As);
    const uint32_t ws_base = (uint32_t)__cvta_generic_to_shared(Ws);

    // ---- stage A ----
    if (A_HALF) {
        const __half* Ah = (const __half*)Ain;
#pragma unroll
        for (int p = 0; p < 8; p++) {
            int i  = tid + p * 256;
            int r  = i >> 4, c8 = i & 15;
            int row = row0 + r;
            uint32_t saddr = as_base + (r * SAH + c8 * 8) * 2;
            const __half* gaddr = Ah + (row < NND ? row : 0) * D + c8 * 8;
            cp_async16(saddr, gaddr, row < NND ? 16 : 0);
        }
    } else {
        const float* Af = (const float*)Ain;
#pragma unroll
        for (int p = 0; p < 16; p++) {
            int i  = tid + p * 256;
            int r  = i >> 5, c4 = i & 31;
            int row = row0 + r;
            float4 v = make_float4(0.f, 0.f, 0.f, 0.f);
            if (row < NND)
                v = *(const float4*)(Af + row * D + c4 * 4);
            __half2 h01 = __floats2half2_rn(v.x, v.y);
            __half2 h23 = __floats2half2_rn(v.z, v.w);
            uint2 u;
            u.x = *(uint32_t*)&h01;
            u.y = *(uint32_t*)&h23;
            *(uint2*)(As + r * SAH + c4 * 4) = u;
        }
    }
    // ---- stage W ----
    if (W_HALF) {
        const __half* Wh = (const __half*)Win;
#pragma unroll
        for (int p = 0; p < (D * BN / 8) / 256; p++) {
            int i = tid + p * 256;
            int r = i / (BN / 8), c8 = i % (BN / 8);
            cp_async16(ws_base + (r * SBH + c8 * 8) * 2, Wh + r * BN + c8 * 8, 16);
        }
        cp_async_commit_wait();
    } else {
        const float* Wf = (const float*)Win;
#pragma unroll
        for (int p = 0; p < (D * BN / 4) / 256; p++) {
            int i = tid + p * 256;
            int r = i / (BN / 4), c4 = i % (BN / 4);
            float4 v = *(const float4*)(Wf + r * BN + c4 * 4);
            __half2 h01 = __floats2half2_rn(v.x, v.y);
            __half2 h23 = __floats2half2_rn(v.z, v.w);
            uint2 u;
            u.x = *(uint32_t*)&h01;
            u.y = *(uint32_t*)&h23;
            *(uint2*)(Ws + r * SBH + c4 * 4) = u;
        }
        if (A_HALF) cp_async_commit_wait();
    }
    __syncthreads();

    float c[NT][4];
#pragma unroll
    for (int j = 0; j < NT; j++)
#pragma unroll
        for (int q = 0; q < 4; q++) c[j][q] = 0.0f;

    const uint32_t a_lane = ((wr0 + (lane & 15)) * SAH + (lane >> 4) * 8) * 2;
    const uint32_t b_lane_row = (lane & 15);
    const uint32_t b_lane_col = ((lane & 16) >> 1);

#pragma unroll
    for (int kk = 0; kk < D; kk += 16) {
        uint32_t a0, a1, a2, a3;
        uint32_t aaddr = as_base + a_lane + kk * 2;
        asm volatile("ldmatrix.sync.aligned.m8n8.x4.shared.b16 {%0,%1,%2,%3}, [%4];"
                     : "=r"(a0), "=r"(a1), "=r"(a2), "=r"(a3) : "r"(aaddr));
#pragma unroll
        for (int jt = 0; jt < NT / 2; jt++) {
            uint32_t b0, b1, b2, b3;
            uint32_t baddr = ws_base +
                ((kk + b_lane_row) * SBH + jt * 16 + b_lane_col) * 2;
            asm volatile("ldmatrix.sync.aligned.m8n8.x4.trans.shared.b16 {%0,%1,%2,%3}, [%4];"
                         : "=r"(b0), "=r"(b1), "=r"(b2), "=r"(b3) : "r"(baddr));
            asm volatile("mma.sync.aligned.m16n8k16.row.col.f32.f16.f16.f32 "
                         "{%0,%1,%2,%3},{%4,%5,%6,%7},{%8,%9},{%0,%1,%2,%3};"
                         : "+f"(c[2*jt][0]), "+f"(c[2*jt][1]),
                           "+f"(c[2*jt][2]), "+f"(c[2*jt][3])
                         : "r"(a0), "r"(a1), "r"(a2), "r"(a3), "r"(b0), "r"(b1));
            asm volatile("mma.sync.aligned.m16n8k16.row.col.f32.f16.f16.f32 "
                         "{%0,%1,%2,%3},{%4,%5,%6,%7},{%8,%9},{%0,%1,%2,%3};"
                         : "+f"(c[2*jt+1][0]), "+f"(c[2*jt+1][1]),
                           "+f"(c[2*jt+1][2]), "+f"(c[2*jt+1][3])
                         : "r"(a0), "r"(a1), "r"(a2), "r"(a3), "r"(b2), "r"(b3));
        }
    }

    const int r1 = row0 + wr0 + (lane >> 2);
    const int r2 = r1 + 8;

    if (EPI == 0) {
        float s1 = (r1 < NND) ? dis[r1] * MSCALE : 0.f;
        float s2 = (r2 < NND) ? dis[r2] * MSCALE : 0.f;
#pragma unroll
        for (int j = 0; j < NT; j++) {
            int col = j * 8 + (lane & 3) * 2;
            if (r1 < NND)
                *(unsigned short*)(Cq + r1 * BN + col) =
                    enc_e4m3x2(c[j][0] * s1, c[j][1] * s1);
            if (r2 < NND)
                *(unsigned short*)(Cq + r2 * BN + col) =
                    enc_e4m3x2(c[j][2] * s2, c[j][3] * s2);
        }
    } else {  // EPI 2: BN=64, NT=8, log_softmax per row
        float t[NT][4];
        float m1 = -1e30f, m2 = -1e30f;
#pragma unroll
        for (int j = 0; j < NT; j++) {
            float2 b = *(const float2*)(biasC + j * 8 + (lane & 3) * 2);
            t[j][0] = c[j][0] + b.x; t[j][1] = c[j][1] + b.y;
            t[j][2] = c[j][2] + b.x; t[j][3] = c[j][3] + b.y;
            m1 = fmaxf(m1, fmaxf(t[j][0], t[j][1]));
            m2 = fmaxf(m2, fmaxf(t[j][2], t[j][3]));
        }
#pragma unroll
        for (int o = 1; o <= 2; o <<= 1) {
            m1 = fmaxf(m1, __shfl_xor_sync(0xFFFFFFFFu, m1, o));
            m2 = fmaxf(m2, __shfl_xor_sync(0xFFFFFFFFu, m2, o));
        }
        float s1 = 0.f, s2 = 0.f;
#pragma unroll
        for (int j = 0; j < NT; j++) {
            s1 += expf(t[j][0] - m1) + expf(t[j][1] - m1);
            s2 += expf(t[j][2] - m2) + expf(t[j][3] - m2);
        }
#pragma unroll
        for (int o = 1; o <= 2; o <<= 1) {
            s1 += __shfl_xor_sync(0xFFFFFFFFu, s1, o);
            s2 += __shfl_xor_sync(0xFFFFFFFFu, s2, o);
        }
        float l1 = m1 + logf(s1);
        float l2 = m2 + logf(s2);
#pragma unroll
        for (int j = 0; j < NT; j++) {
            int col = j * 8 + (lane & 3) * 2;
            if (r1 < NND) {
                float2 r; r.x = t[j][0] - l1; r.y = t[j][1] - l1;
                *(float2*)(Cf + r1 * BN + col) = r;
            }
            if (r2 < NND) {
                float2 r; r.x = t[j][2] - l2; r.y = t[j][3] - l2;
                *(float2*)(Cf + r2 * BN + col) = r;
            }
        }
    }
}

// ---------------- CSR gather (fp8 pre-scaled messages, fp16 accum) + finalize -------
// 8-deep scalar-index batches (the measured sweet spot; 16-deep regressed via
// cross-CTA L1tex-queue contention).  h[v] = half(relu(dis[v]/16 * acc + bias))

__device__ __forceinline__ void acc_u32(__half2& a0, __half2& a1, uint32_t u) {
    a0 = __hadd2(a0, dec_e4m3x2((unsigned short)u));
    a1 = __hadd2(a1, dec_e4m3x2((unsigned short)(u >> 16)));
}

__global__ __launch_bounds__(256)
void k_gather_fin(const unsigned char* __restrict__ g, const float* __restrict__ dis,
                  const float* __restrict__ bias, __half* __restrict__ h)
{
    int node = (blockIdx.x * blockDim.x + threadIdx.x) >> 5;
    int lane = threadIdx.x & 31;
    if (node >= NND) return;
    int beg = row_ptr[node];
    int end = row_ptr[node + 1];
    const uint32_t* gp = (const uint32_t*)g;   // 4 fp8 per lane

    __half2 acc0 = __float2half2_rn(0.f);
    __half2 acc1 = __float2half2_rn(0.f);
    acc_u32(acc0, acc1, gp[node * 32 + lane]);   // self-loop message

    int e = beg;
    for (; e + 8 <= end; e += 8) {
        int s0 = __ldg(&csr_src[e + 0]);
        int s1 = __ldg(&csr_src[e + 1]);
        int s2 = __ldg(&csr_src[e + 2]);
        int s3 = __ldg(&csr_src[e + 3]);
        int s4 = __ldg(&csr_src[e + 4]);
        int s5 = __ldg(&csr_src[e + 5]);
        int s6 = __ldg(&csr_src[e + 6]);
        int s7 = __ldg(&csr_src[e + 7]);
        uint32_t u0 = gp[s0 * 32 + lane];
        uint32_t u1 = gp[s1 * 32 + lane];
        uint32_t u2 = gp[s2 * 32 + lane];
        uint32_t u3 = gp[s3 * 32 + lane];
        uint32_t u4 = gp[s4 * 32 + lane];
        uint32_t u5 = gp[s5 * 32 + lane];
        uint32_t u6 = gp[s6 * 32 + lane];
        uint32_t u7 = gp[s7 * 32 + lane];
        acc_u32(acc0, acc1, u0); acc_u32(acc0, acc1, u1);
        acc_u32(acc0, acc1, u2); acc_u32(acc0, acc1, u3);
        acc_u32(acc0, acc1, u4); acc_u32(acc0, acc1, u5);
        acc_u32(acc0, acc1, u6); acc_u32(acc0, acc1, u7);
    }
    for (; e < end; e++)
        acc_u32(acc0, acc1, gp[__ldg(&csr_src[e]) * 32 + lane]);

    float sc = dis[node] * INV_MSCALE;
    float2 f0 = __half22float2(acc0);
    float2 f1 = __half22float2(acc1);
    float4 b = ((const float4*)bias)[lane];
    __half2 r0 = __floats2half2_rn(fmaxf(fmaf(f0.x, sc, b.x), 0.f),
                                   fmaxf(fmaf(f0.y, sc, b.y), 0.f));
    __half2 r1 = __floats2half2_rn(fmaxf(fmaf(f1.x, sc, b.z), 0.f),
                                   fmaxf(fmaf(f1.y, sc, b.w), 0.f));
    uint2 u;
    u.x = *(uint32_t*)&r0;
    u.y = *(uint32_t*)&r1;
    ((uint2*)h)[node * 32 + lane] = u;
}

// ---------------- launch ----------------

extern "C" void kernel_launch(void* const* d_in, const int* in_sizes, int n_in,
                              void* d_out, int out_size)
{
    const float* x   = (const float*)d_in[0];
    const int*   ei  = (const int*)d_in[1];
    const int*   src = ei;
    const int*   dst = ei + NE;
    const float* W1  = (const float*)d_in[2];
    const float* b1  = (const float*)d_in[3];
    const float* W2  = (const float*)d_in[4];
    const float* b2  = (const float*)d_in[5];
    const float* Wp1 = (const float*)d_in[6];
    const float* bp1 = (const float*)d_in[7];
    const float* Wp2 = (const float*)d_in[8];
    const float* bp2 = (const float*)d_in[9];
    float* out = (float*)d_out;

    unsigned char *g_p, *g2_p;
    __half *h_p, *w2h_p, *wfh_p;
    float *dis_p, *bf_p;
    int *deg_p;
    cudaGetSymbolAddress((void**)&g_p,   g_buf);
    cudaGetSymbolAddress((void**)&g2_p,  g2_buf);
    cudaGetSymbolAddress((void**)&h_p,   h_buf);
    cudaGetSymbolAddress((void**)&dis_p, dis_buf);
    cudaGetSymbolAddress((void**)&w2h_p, W2h_buf);
    cudaGetSymbolAddress((void**)&wfh_p, Wfh_buf);
    cudaGetSymbolAddress((void**)&bf_p,  bF_buf);
    cudaGetSymbolAddress((void**)&deg_p, deg_buf);

    const int SM_BN128 = (128 * (D + 8) + D * (128 + 8)) * 2;  // 69632
    const int SM_BN64  = (128 * (D + 8) + D * (64 + 8))  * 2;  // 53248

    static cudaStream_t s2 = nullptr;
    static cudaEvent_t ev_fork, ev_dis, ev_csr, ev_w;
    if (!s2) {
        cudaStreamCreateWithFlags(&s2, cudaStreamNonBlocking);
        cudaEventCreateWithFlags(&ev_fork, cudaEventDisableTiming);
        cudaEventCreateWithFlags(&ev_dis,  cudaEventDisableTiming);
        cudaEventCreateWithFlags(&ev_csr,  cudaEventDisableTiming);
        cudaEventCreateWithFlags(&ev_w,    cudaEventDisableTiming);
        cudaFuncSetAttribute((const void*)hgemm<128, false, false, 0>,
                             cudaFuncAttributeMaxDynamicSharedMemorySize, SM_BN128);
        cudaFuncSetAttribute((const void*)hgemm<128, true, true, 0>,
                             cudaFuncAttributeMaxDynamicSharedMemorySize, SM_BN128);
        cudaFuncSetAttribute((const void*)hgemm<64, true, true, 2>,
                             cudaFuncAttributeMaxDynamicSharedMemorySize, SM_BN64);
    }

    const int GEMM_BLOCKS   = (NND + 127) / 128;       // 782
    const int GATHER_BLOCKS = (NND * 32 + 255) / 256;  // 12500
    const int EDGE4_BLOCKS  = (NE / 4 + 255) / 256;    // 1563

    // ---- fork: CSR build first on s2 (critical), then weight prep ----
    cudaEventRecord(ev_fork, 0);
    cudaStreamWaitEvent(s2, ev_fork, 0);

    cudaMemsetAsync(deg_p, 0, NND * sizeof(int), s2);
    k_count_deg<<<EDGE4_BLOCKS, 256, 0, s2>>>(dst);
    k_scan1<<<SCAN_BLOCKS, SCB, 0, s2>>>();     // also writes dis
    cudaEventRecord(ev_dis, s2);
    k_scan3<<<SCAN_BLOCKS, SCB, 0, s2>>>();     // self-computed block offsets
    k_fill<<<EDGE4_BLOCKS, 256, 0, s2>>>(src, dst);
    cudaEventRecord(ev_csr, s2);
    k_wprep<<<(D * D + D * 64 + 255) / 256, 256, 0, s2>>>(W2, Wp1, bp1, Wp2, bp2);
    cudaEventRecord(ev_w, s2);

    // main: GEMM1 (fp32 A + fp32 W converted in-staging): g = e4m3((x@W1)*dis*16)
    cudaStreamWaitEvent(0, ev_dis, 0);
    hgemm<128, false, false, 0><<<GEMM_BLOCKS, 256, SM_BN128>>>(
        x, W1, nullptr, dis_p, g_p, nullptr);

    cudaStreamWaitEvent(0, ev_csr, 0);

    // ---- layer 1 aggregate: h = half(relu(dis/16*gather(g) + b1)) ----
    k_gather_fin<<<GATHER_BLOCKS, 256>>>(g_p, dis_p, b1, h_p);

    cudaStreamWaitEvent(0, ev_w, 0);

    // ---- layer 2: g2 = e4m3((h@W2)*dis*16) ; h = half(relu(dis/16*gather(g2) + b2)) ----
    hgemm<128, true, true, 0><<<GEMM_BLOCKS, 256, SM_BN128>>>(
        h_p, w2h_p, nullptr, dis_p, g2_p, nullptr);
    k_gather_fin<<<GATHER_BLOCKS, 256>>>(g2_p, dis_p, b2, h_p);

    // ---- fused head + log_softmax: out = logsoftmax(h @ Wf + bF) ----
    hgemm<64, true, true, 2><<<GEMM_BLOCKS, 256, SM_BN64>>>(
        h_p, wfh_p, bf_p, dis_p, nullptr, out);
}

// round 16
// speedup vs baseline: 1.2712x; 1.0030x over previous
#include <cuda_runtime.h>
#include <cuda_fp16.h>
#include <math.h>
#include <stdint.h>

#define NND 100000
#define NE  1600000
#define D   128
#define MSCALE 16.0f
#define INV_MSCALE (1.0f / 16.0f)

// Scratch (static device globals — no runtime allocation allowed)
__device__ unsigned char g_buf [NND * D];  // layer-1 messages (e4m3, x16, pre-scaled by dis_src)
__device__ unsigned char g2_buf[NND * D];  // layer-2 messages (e4m3, x16, pre-scaled by dis_src)
__device__ __half h_buf [NND * D];         // activations (fp16)
__device__ float dis_buf[NND];
__device__ int   deg_buf[NND];
__device__ int   scan_tmp[NND];
__device__ int   row_ptr[NND + 1];
__device__ int   cursor[NND];
__device__ int   csr_src[NE];
__device__ int   bsum[256];
__device__ __half W2h_buf[D * D];
__device__ __half Wfh_buf[D * 64];   // fused head weight  Wp1@Wp2 (fp16)
__device__ float bF_buf[64];         // fused head bias    bp1@Wp2 + bp2

// ---------------- cp.async helpers ----------------

__device__ __forceinline__ void cp_async16(uint32_t saddr, const void* gaddr, int szbytes) {
    asm volatile("cp.async.cg.shared.global [%0], [%1], 16, %2;"
                 :: "r"(saddr), "l"(gaddr), "r"(szbytes));
}
__device__ __forceinline__ void cp_async_commit_wait() {
    asm volatile("cp.async.commit_group;");
    asm volatile("cp.async.wait_group 0;");
}

// ---------------- fp8 helpers ----------------

__device__ __forceinline__ unsigned short enc_e4m3x2(float lo, float hi) {
    unsigned short u;
    asm("cvt.rn.satfinite.e4m3x2.f32 %0, %1, %2;" : "=h"(u) : "f"(hi), "f"(lo));
    return u;
}
__device__ __forceinline__ __half2 dec_e4m3x2(unsigned short u) {
    uint32_t r;
    asm("cvt.rn.f16x2.e4m3x2 %0, %1;" : "=r"(r) : "h"(u));
    return *(__half2*)&r;
}

// ---------------- degree / normalization / CSR build ----------------

__global__ void k_count_deg(const int* __restrict__ dst) {
    int t = blockIdx.x * blockDim.x + threadIdx.x;
    if (t * 4 >= NE) return;
    int4 d = *(const int4*)(dst + t * 4);
    atomicAdd(&deg_buf[d.x], 1);
    atomicAdd(&deg_buf[d.y], 1);
    atomicAdd(&deg_buf[d.z], 1);
    atomicAdd(&deg_buf[d.w], 1);
}

#define SCB 512
#define SCAN_BLOCKS ((NND + SCB - 1) / SCB)   // 196

// block-local inclusive scan of deg; also writes dis = rsqrt(deg+1)
__global__ __launch_bounds__(SCB) void k_scan1() {
    __shared__ int sm[SCB];
    int i = blockIdx.x * SCB + threadIdx.x;
    int v = (i < NND) ? deg_buf[i] : 0;
    sm[threadIdx.x] = v;
    if (i < NND) dis_buf[i] = rsqrtf((float)(v + 1));
    __syncthreads();
#pragma unroll
    for (int off = 1; off < SCB; off <<= 1) {
        int t = (threadIdx.x >= off) ? sm[threadIdx.x - off] : 0;
        __syncthreads();
        sm[threadIdx.x] += t;
        __syncthreads();
    }
    if (i < NND) scan_tmp[i] = sm[threadIdx.x];
    if (threadIdx.x == SCB - 1) bsum[blockIdx.x] = sm[SCB - 1];
}

// per-block offset computed in-block from raw bsum[] (replaces scan2)
__global__ __launch_bounds__(SCB) void k_scan3() {
    __shared__ int wsum[SCB / 32];
    __shared__ int blk_off;
    int t    = threadIdx.x;
    int lane = t & 31;
    int v = (t < blockIdx.x && t < SCAN_BLOCKS) ? bsum[t] : 0;
#pragma unroll
    for (int o = 16; o; o >>= 1) v += __shfl_xor_sync(0xFFFFFFFFu, v, o);
    if (lane == 0) wsum[t >> 5] = v;
    __syncthreads();
    if (t == 0) {
        int s = 0;
#pragma unroll
        for (int w = 0; w < SCB / 32; w++) s += wsum[w];
        blk_off = s;
    }
    __syncthreads();
    int i = blockIdx.x * SCB + t;
    if (i >= NND) return;
    int dg  = deg_buf[i];
    int inc = scan_tmp[i] + blk_off;
    int st  = inc - dg;
    row_ptr[i] = st;
    cursor[i]  = st;
    if (i == NND - 1) row_ptr[NND] = inc;
}

__global__ void k_fill(const int* __restrict__ src, const int* __restrict__ dst) {
    int t = blockIdx.x * blockDim.x + threadIdx.x;
    if (t * 4 >= NE) return;
    int4 s = *(const int4*)(src + t * 4);
    int4 d = *(const int4*)(dst + t * 4);
    csr_src[atomicAdd(&cursor[d.x], 1)] = s.x;
    csr_src[atomicAdd(&cursor[d.y], 1)] = s.y;
    csr_src[atomicAdd(&cursor[d.z], 1)] = s.z;
    csr_src[atomicAdd(&cursor[d.w], 1)] = s.w;
}

// ---------------- weight prep: W2->fp16 + fused head weight/bias ----------------

__global__ __launch_bounds__(256) void k_wprep(const float* __restrict__ W2,
                                               const float* __restrict__ Wp1,
                                               const float* __restrict__ bp1,
                                               const float* __restrict__ Wp2,
                                               const float* __restrict__ bp2)
{
    int i = blockIdx.x * blockDim.x + threadIdx.x;
    if (i < D * D) {
        W2h_buf[i] = __float2half_rn(W2[i]);
        return;
    }
    int j = i - D * D;
    if (j >= D * 64) return;
    int k = j >> 6, n = j & 63;
    float s = 0.0f;
#pragma unroll 8
    for (int t = 0; t < D; t++)
        s = fmaf(Wp1[k * D + t], Wp2[t * 64 + n], s);
    Wfh_buf[j] = __float2half_rn(s);
    if (k == 0) {
        float b = bp2[n];
#pragma unroll 8
        for (int t = 0; t < D; t++)
            b = fmaf(bp1[t], Wp2[t * 64 + n], b);
        bF_buf[n] = b;
    }
}

// ---------------- HMMA GEMM (full-K resident): C = A[128rows,128] @ W[128,BN] --------
// 256 threads = 8 warps; warp w owns rows [w*16, w*16+16); mma.sync m16n8k16 fp16->fp32.
// EPI 0: Cq = e4m3(acc * dis[row] * MSCALE)  (fp8 message write)
// EPI 2: Cf = log_softmax(acc + biasC) over row (BN=64)

template <int BN, bool A_HALF, bool W_HALF, int EPI>
__global__ __launch_bounds__(256)
void hgemm(const void* __restrict__ Ain,
           const void* __restrict__ Win,
           const float* __restrict__ biasC,
           const float* __restrict__ dis,
           unsigned char* __restrict__ Cq,
           float* __restrict__ Cf)
{
    constexpr int SAH = D + 8;
    constexpr int SBH = BN + 8;
    constexpr int NT  = BN / 8;
    extern __shared__ __align__(16) __half smem[];
    __half* As = smem;
    __half* Ws = smem + 128 * SAH;

    const int tid  = threadIdx.x;
    const int wid  = tid >> 5;
    const int lane = tid & 31;
    const int row0 = blockIdx.x * 128;
    const int wr0  = wid * 16;

    const uint32_t as_base = (uint32_t)__cvta_generic_to_shared(As);
    const uint32_t ws_base = (uint32_t)__cvta_generic_to_shared(Ws);

    // ---- stage A ----
    if (A_HALF) {
        const __half* Ah = (const __half*)Ain;
#pragma unroll
        for (int p = 0; p < 8; p++) {
            int i  = tid + p * 256;
            int r  = i >> 4, c8 = i & 15;
            int row = row0 + r;
            uint32_t saddr = as_base + (r * SAH + c8 * 8) * 2;
            const __half* gaddr = Ah + (row < NND ? row : 0) * D + c8 * 8;
            cp_async16(saddr, gaddr, row < NND ? 16 : 0);
        }
    } else {
        const float* Af = (const float*)Ain;
#pragma unroll
        for (int p = 0; p < 16; p++) {
            int i  = tid + p * 256;
            int r  = i >> 5, c4 = i & 31;
            int row = row0 + r;
            float4 v = make_float4(0.f, 0.f, 0.f, 0.f);
            if (row < NND)
                v = *(const float4*)(Af + row * D + c4 * 4);
            __half2 h01 = __floats2half2_rn(v.x, v.y);
            __half2 h23 = __floats2half2_rn(v.z, v.w);
            uint2 u;
            u.x = *(uint32_t*)&h01;
            u.y = *(uint32_t*)&h23;
            *(uint2*)(As + r * SAH + c4 * 4) = u;
        }
    }
    // ---- stage W ----
    if (W_HALF) {
        const __half* Wh = (const __half*)Win;
#pragma unroll
        for (int p = 0; p < (D * BN / 8) / 256; p++) {
            int i = tid + p * 256;
            int r = i / (BN / 8), c8 = i % (BN / 8);
            cp_async16(ws_base + (r * SBH + c8 * 8) * 2, Wh + r * BN + c8 * 8, 16);
        }
        cp_async_commit_wait();
    } else {
        const float* Wf = (const float*)Win;
#pragma unroll
        for (int p = 0; p < (D * BN / 4) / 256; p++) {
            int i = tid + p * 256;
            int r = i / (BN / 4), c4 = i % (BN / 4);
            float4 v = *(const float4*)(Wf + r * BN + c4 * 4);
            __half2 h01 = __floats2half2_rn(v.x, v.y);
            __half2 h23 = __floats2half2_rn(v.z, v.w);
            uint2 u;
            u.x = *(uint32_t*)&h01;
            u.y = *(uint32_t*)&h23;
            *(uint2*)(Ws + r * SBH + c4 * 4) = u;
        }
        if (A_HALF) cp_async_commit_wait();
    }
    __syncthreads();

    float c[NT][4];
#pragma unroll
    for (int j = 0; j < NT; j++)
#pragma unroll
        for (int q = 0; q < 4; q++) c[j][q] = 0.0f;

    const uint32_t a_lane = ((wr0 + (lane & 15)) * SAH + (lane >> 4) * 8) * 2;
    const uint32_t b_lane_row = (lane & 15);
    const uint32_t b_lane_col = ((lane & 16) >> 1);

#pragma unroll
    for (int kk = 0; kk < D; kk += 16) {
        uint32_t a0, a1, a2, a3;
        uint32_t aaddr = as_base + a_lane + kk * 2;
        asm volatile("ldmatrix.sync.aligned.m8n8.x4.shared.b16 {%0,%1,%2,%3}, [%4];"
                     : "=r"(a0), "=r"(a1), "=r"(a2), "=r"(a3) : "r"(aaddr));
#pragma unroll
        for (int jt = 0; jt < NT / 2; jt++) {
            uint32_t b0, b1, b2, b3;
            uint32_t baddr = ws_base +
                ((kk + b_lane_row) * SBH + jt * 16 + b_lane_col) * 2;
            asm volatile("ldmatrix.sync.aligned.m8n8.x4.trans.shared.b16 {%0,%1,%2,%3}, [%4];"
                         : "=r"(b0), "=r"(b1), "=r"(b2), "=r"(b3) : "r"(baddr));
            asm volatile("mma.sync.aligned.m16n8k16.row.col.f32.f16.f16.f32 "
                         "{%0,%1,%2,%3},{%4,%5,%6,%7},{%8,%9},{%0,%1,%2,%3};"
                         : "+f"(c[2*jt][0]), "+f"(c[2*jt][1]),
                           "+f"(c[2*jt][2]), "+f"(c[2*jt][3])
                         : "r"(a0), "r"(a1), "r"(a2), "r"(a3), "r"(b0), "r"(b1));
            asm volatile("mma.sync.aligned.m16n8k16.row.col.f32.f16.f16.f32 "
                         "{%0,%1,%2,%3},{%4,%5,%6,%7},{%8,%9},{%0,%1,%2,%3};"
                         : "+f"(c[2*jt+1][0]), "+f"(c[2*jt+1][1]),
                           "+f"(c[2*jt+1][2]), "+f"(c[2*jt+1][3])
                         : "r"(a0), "r"(a1), "r"(a2), "r"(a3), "r"(b2), "r"(b3));
        }
    }

    const int r1 = row0 + wr0 + (lane >> 2);
    const int r2 = r1 + 8;

    if (EPI == 0) {
        float s1 = (r1 < NND) ? dis[r1] * MSCALE : 0.f;
        float s2 = (r2 < NND) ? dis[r2] * MSCALE : 0.f;
#pragma unroll
        for (int j = 0; j < NT; j++) {
            int col = j * 8 + (lane & 3) * 2;
            if (r1 < NND)
                *(unsigned short*)(Cq + r1 * BN + col) =
                    enc_e4m3x2(c[j][0] * s1, c[j][1] * s1);
            if (r2 < NND)
                *(unsigned short*)(Cq + r2 * BN + col) =
                    enc_e4m3x2(c[j][2] * s2, c[j][3] * s2);
        }
    } else {  // EPI 2: BN=64, NT=8, log_softmax per row
        float t[NT][4];
        float m1 = -1e30f, m2 = -1e30f;
#pragma unroll
        for (int j = 0; j < NT; j++) {
            float2 b = *(const float2*)(biasC + j * 8 + (lane & 3) * 2);
            t[j][0] = c[j][0] + b.x; t[j][1] = c[j][1] + b.y;
            t[j][2] = c[j][2] + b.x; t[j][3] = c[j][3] + b.y;
            m1 = fmaxf(m1, fmaxf(t[j][0], t[j][1]));
            m2 = fmaxf(m2, fmaxf(t[j][2], t[j][3]));
        }
#pragma unroll
        for (int o = 1; o <= 2; o <<= 1) {
            m1 = fmaxf(m1, __shfl_xor_sync(0xFFFFFFFFu, m1, o));
            m2 = fmaxf(m2, __shfl_xor_sync(0xFFFFFFFFu, m2, o));
        }
        float s1 = 0.f, s2 = 0.f;
#pragma unroll
        for (int j = 0; j < NT; j++) {
            s1 += expf(t[j][0] - m1) + expf(t[j][1] - m1);
            s2 += expf(t[j][2] - m2) + expf(t[j][3] - m2);
        }
#pragma unroll
        for (int o = 1; o <= 2; o <<= 1) {
            s1 += __shfl_xor_sync(0xFFFFFFFFu, s1, o);
            s2 += __shfl_xor_sync(0xFFFFFFFFu, s2, o);
        }
        float l1 = m1 + logf(s1);
        float l2 = m2 + logf(s2);
#pragma unroll
        for (int j = 0; j < NT; j++) {
            int col = j * 8 + (lane & 3) * 2;
            if (r1 < NND) {
                float2 r; r.x = t[j][0] - l1; r.y = t[j][1] - l1;
                *(float2*)(Cf + r1 * BN + col) = r;
            }
            if (r2 < NND) {
                float2 r; r.x = t[j][2] - l2; r.y = t[j][3] - l2;
                *(float2*)(Cf + r2 * BN + col) = r;
            }
        }
    }
}

// ---------------- CSR gather (fp8 pre-scaled messages, fp16 accum) + finalize -------
// 8-deep scalar-index batches (the measured sweet spot; 16-deep regressed via
// cross-CTA L1tex-queue contention).  h[v] = half(relu(dis[v]/16 * acc + bias))

__device__ __forceinline__ void acc_u32(__half2& a0, __half2& a1, uint32_t u) {
    a0 = __hadd2(a0, dec_e4m3x2((unsigned short)u));
    a1 = __hadd2(a1, dec_e4m3x2((unsigned short)(u >> 16)));
}

__global__ __launch_bounds__(256)
void k_gather_fin(const unsigned char* __restrict__ g, const float* __restrict__ dis,
                  const float* __restrict__ bias, __half* __restrict__ h)
{
    int node = (blockIdx.x * blockDim.x + threadIdx.x) >> 5;
    int lane = threadIdx.x & 31;
    if (node >= NND) return;
    int beg = row_ptr[node];
    int end = row_ptr[node + 1];
    const uint32_t* gp = (const uint32_t*)g;   // 4 fp8 per lane

    __half2 acc0 = __float2half2_rn(0.f);
    __half2 acc1 = __float2half2_rn(0.f);
    acc_u32(acc0, acc1, gp[node * 32 + lane]);   // self-loop message

    int e = beg;
    for (; e + 8 <= end; e += 8) {
        int s0 = __ldg(&csr_src[e + 0]);
        int s1 = __ldg(&csr_src[e + 1]);
        int s2 = __ldg(&csr_src[e + 2]);
        int s3 = __ldg(&csr_src[e + 3]);
        int s4 = __ldg(&csr_src[e + 4]);
        int s5 = __ldg(&csr_src[e + 5]);
        int s6 = __ldg(&csr_src[e + 6]);
        int s7 = __ldg(&csr_src[e + 7]);
        uint32_t u0 = gp[s0 * 32 + lane];
        uint32_t u1 = gp[s1 * 32 + lane];
        uint32_t u2 = gp[s2 * 32 + lane];
        uint32_t u3 = gp[s3 * 32 + lane];
        uint32_t u4 = gp[s4 * 32 + lane];
        uint32_t u5 = gp[s5 * 32 + lane];
        uint32_t u6 = gp[s6 * 32 + lane];
        uint32_t u7 = gp[s7 * 32 + lane];
        acc_u32(acc0, acc1, u0); acc_u32(acc0, acc1, u1);
        acc_u32(acc0, acc1, u2); acc_u32(acc0, acc1, u3);
        acc_u32(acc0, acc1, u4); acc_u32(acc0, acc1, u5);
        acc_u32(acc0, acc1, u6); acc_u32(acc0, acc1, u7);
    }
    for (; e < end; e++)
        acc_u32(acc0, acc1, gp[__ldg(&csr_src[e]) * 32 + lane]);

    float sc = dis[node] * INV_MSCALE;
    float2 f0 = __half22float2(acc0);
    float2 f1 = __half22float2(acc1);
    float4 b = ((const float4*)bias)[lane];
    __half2 r0 = __floats2half2_rn(fmaxf(fmaf(f0.x, sc, b.x), 0.f),
                                   fmaxf(fmaf(f0.y, sc, b.y), 0.f));
    __half2 r1 = __floats2half2_rn(fmaxf(fmaf(f1.x, sc, b.z), 0.f),
                                   fmaxf(fmaf(f1.y, sc, b.w), 0.f));
    uint2 u;
    u.x = *(uint32_t*)&r0;
    u.y = *(uint32_t*)&r1;
    ((uint2*)h)[node * 32 + lane] = u;
}

// ---------------- launch ----------------

extern "C" void kernel_launch(void* const* d_in, const int* in_sizes, int n_in,
                              void* d_out, int out_size)
{
    const float* x   = (const float*)d_in[0];
    const int*   ei  = (const int*)d_in[1];
    const int*   src = ei;
    const int*   dst = ei + NE;
    const float* W1  = (const float*)d_in[2];
    const float* b1  = (const float*)d_in[3];
    const float* W2  = (const float*)d_in[4];
    const float* b2  = (const float*)d_in[5];
    const float* Wp1 = (const float*)d_in[6];
    const float* bp1 = (const float*)d_in[7];
    const float* Wp2 = (const float*)d_in[8];
    const float* bp2 = (const float*)d_in[9];
    float* out = (float*)d_out;

    unsigned char *g_p, *g2_p;
    __half *h_p, *w2h_p, *wfh_p;
    float *dis_p, *bf_p;
    int *deg_p;
    cudaGetSymbolAddress((void**)&g_p,   g_buf);
    cudaGetSymbolAddress((void**)&g2_p,  g2_buf);
    cudaGetSymbolAddress((void**)&h_p,   h_buf);
    cudaGetSymbolAddress((void**)&dis_p, dis_buf);
    cudaGetSymbolAddress((void**)&w2h_p, W2h_buf);
    cudaGetSymbolAddress((void**)&wfh_p, Wfh_buf);
    cudaGetSymbolAddress((void**)&bf_p,  bF_buf);
    cudaGetSymbolAddress((void**)&deg_p, deg_buf);

    const int SM_BN128 = (128 * (D + 8) + D * (128 + 8)) * 2;  // 69632
    const int SM_BN64  = (128 * (D + 8) + D * (64 + 8))  * 2;  // 53248

    static cudaStream_t s2 = nullptr;
    static cudaEvent_t ev_fork, ev_dis, ev_csr, ev_w;
    if (!s2) {
        cudaStreamCreateWithFlags(&s2, cudaStreamNonBlocking);
        cudaEventCreateWithFlags(&ev_fork, cudaEventDisableTiming);
        cudaEventCreateWithFlags(&ev_dis,  cudaEventDisableTiming);
        cudaEventCreateWithFlags(&ev_csr,  cudaEventDisableTiming);
        cudaEventCreateWithFlags(&ev_w,    cudaEventDisableTiming);
        cudaFuncSetAttribute((const void*)hgemm<128, false, false, 0>,
                             cudaFuncAttributeMaxDynamicSharedMemorySize, SM_BN128);
        cudaFuncSetAttribute((const void*)hgemm<128, true, true, 0>,
                             cudaFuncAttributeMaxDynamicSharedMemorySize, SM_BN128);
        cudaFuncSetAttribute((const void*)hgemm<64, true, true, 2>,
                             cudaFuncAttributeMaxDynamicSharedMemorySize, SM_BN64);
    }

    const int GEMM_BLOCKS   = (NND + 127) / 128;       // 782
    const int GATHER_BLOCKS = (NND * 32 + 255) / 256;  // 12500
    const int EDGE4_BLOCKS  = (NE / 4 + 255) / 256;    // 1563

    // ---- fork: CSR build first on s2 (critical), then weight prep ----
    cudaEventRecord(ev_fork, 0);
    cudaStreamWaitEvent(s2, ev_fork, 0);

    cudaMemsetAsync(deg_p, 0, NND * sizeof(int), s2);
    k_count_deg<<<EDGE4_BLOCKS, 256, 0, s2>>>(dst);
    k_scan1<<<SCAN_BLOCKS, SCB, 0, s2>>>();     // also writes dis
    cudaEventRecord(ev_dis, s2);
    k_scan3<<<SCAN_BLOCKS, SCB, 0, s2>>>();     // self-computed block offsets
    k_fill<<<EDGE4_BLOCKS, 256, 0, s2>>>(src, dst);
    cudaEventRecord(ev_csr, s2);
    k_wprep<<<(D * D + D * 64 + 255) / 256, 256, 0, s2>>>(W2, Wp1, bp1, Wp2, bp2);
    cudaEventRecord(ev_w, s2);

    // main: GEMM1 (fp32 A + fp32 W converted in-staging): g = e4m3((x@W1)*dis*16)
    cudaStreamWaitEvent(0, ev_dis, 0);
    hgemm<128, false, false, 0><<<GEMM_BLOCKS, 256, SM_BN128>>>(
        x, W1, nullptr, dis_p, g_p, nullptr);

    cudaStreamWaitEvent(0, ev_csr, 0);

    // ---- layer 1 aggregate: h = half(relu(dis/16*gather(g) + b1)) ----
    k_gather_fin<<<GATHER_BLOCKS, 256>>>(g_p, dis_p, b1, h_p);

    cudaStreamWaitEvent(0, ev_w, 0);

    // ---- layer 2: g2 = e4m3((h@W2)*dis*16) ; h = half(relu(dis/16*gather(g2) + b2)) ----
    hgemm<128, true, true, 0><<<GEMM_BLOCKS, 256, SM_BN128>>>(
        h_p, w2h_p, nullptr, dis_p, g2_p, nullptr);
    k_gather_fin<<<GATHER_BLOCKS, 256>>>(g2_p, dis_p, b2, h_p);

    // ---- fused head + log_softmax: out = logsoftmax(h @ Wf + bF) ----
    hgemm<64, true, true, 2><<<GEMM_BLOCKS, 256, SM_BN64>>>(
        h_p, wfh_p, bf_p, dis_p, nullptr, out);
}

// round 17
// speedup vs baseline: 1.2722x; 1.0008x over previous
#include <cuda_runtime.h>
#include <cuda_fp16.h>
#include <math.h>
#include <stdint.h>

#define NND 100000
#define NE  1600000
#define D   128
#define MSCALE 16.0f
#define INV_MSCALE (1.0f / 16.0f)

// Scratch (static device globals — no runtime allocation allowed)
__device__ unsigned char g_buf [NND * D];  // layer-1 messages (e4m3, x16, pre-scaled by dis_src)
__device__ unsigned char g2_buf[NND * D];  // layer-2 messages (e4m3, x16, pre-scaled by dis_src)
__device__ __half h_buf [NND * D];         // activations (fp16)
__device__ float dis_buf[NND];
__device__ int   deg_buf[NND];
__device__ int   scan_tmp[NND];
__device__ int   row_ptr[NND + 1];
__device__ int   cursor[NND];
__device__ int   csr_src[NE];
__device__ int   bsum[256];
__device__ __half W2h_buf[D * D];
__device__ __half Wfh_buf[D * 64];   // fused head weight  Wp1@Wp2 (fp16)
__device__ float bF_buf[64];         // fused head bias    bp1@Wp2 + bp2

// ---------------- cp.async helpers ----------------

__device__ __forceinline__ void cp_async16(uint32_t saddr, const void* gaddr, int szbytes) {
    asm volatile("cp.async.cg.shared.global [%0], [%1], 16, %2;"
                 :: "r"(saddr), "l"(gaddr), "r"(szbytes));
}
__device__ __forceinline__ void cp_async_commit_wait() {
    asm volatile("cp.async.commit_group;");
    asm volatile("cp.async.wait_group 0;");
}

// ---------------- fp8 helpers ----------------

__device__ __forceinline__ unsigned short enc_e4m3x2(float lo, float hi) {
    unsigned short u;
    asm("cvt.rn.satfinite.e4m3x2.f32 %0, %1, %2;" : "=h"(u) : "f"(hi), "f"(lo));
    return u;
}
__device__ __forceinline__ __half2 dec_e4m3x2(unsigned short u) {
    uint32_t r;
    asm("cvt.rn.f16x2.e4m3x2 %0, %1;" : "=r"(r) : "h"(u));
    return *(__half2*)&r;
}

// ---------------- degree / normalization / CSR build ----------------

__global__ void k_count_deg(const int* __restrict__ dst) {
    int t = blockIdx.x * blockDim.x + threadIdx.x;
    if (t * 4 >= NE) return;
    int4 d = *(const int4*)(dst + t * 4);
    atomicAdd(&deg_buf[d.x], 1);
    atomicAdd(&deg_buf[d.y], 1);
    atomicAdd(&deg_buf[d.z], 1);
    atomicAdd(&deg_buf[d.w], 1);
}

#define SCB 512
#define SCAN_BLOCKS ((NND + SCB - 1) / SCB)   // 196

// block-local inclusive scan of deg; also writes dis = rsqrt(deg+1)
__global__ __launch_bounds__(SCB) void k_scan1() {
    __shared__ int sm[SCB];
    int i = blockIdx.x * SCB + threadIdx.x;
    int v = (i < NND) ? deg_buf[i] : 0;
    sm[threadIdx.x] = v;
    if (i < NND) dis_buf[i] = rsqrtf((float)(v + 1));
    __syncthreads();
#pragma unroll
    for (int off = 1; off < SCB; off <<= 1) {
        int t = (threadIdx.x >= off) ? sm[threadIdx.x - off] : 0;
        __syncthreads();
        sm[threadIdx.x] += t;
        __syncthreads();
    }
    if (i < NND) scan_tmp[i] = sm[threadIdx.x];
    if (threadIdx.x == SCB - 1) bsum[blockIdx.x] = sm[SCB - 1];
}

// per-block offset computed in-block from raw bsum[] (replaces scan2)
__global__ __launch_bounds__(SCB) void k_scan3() {
    __shared__ int wsum[SCB / 32];
    __shared__ int blk_off;
    int t    = threadIdx.x;
    int lane = t & 31;
    int v = (t < blockIdx.x && t < SCAN_BLOCKS) ? bsum[t] : 0;
#pragma unroll
    for (int o = 16; o; o >>= 1) v += __shfl_xor_sync(0xFFFFFFFFu, v, o);
    if (lane == 0) wsum[t >> 5] = v;
    __syncthreads();
    if (t == 0) {
        int s = 0;
#pragma unroll
        for (int w = 0; w < SCB / 32; w++) s += wsum[w];
        blk_off = s;
    }
    __syncthreads();
    int i = blockIdx.x * SCB + t;
    if (i >= NND) return;
    int dg  = deg_buf[i];
    int inc = scan_tmp[i] + blk_off;
    int st  = inc - dg;
    row_ptr[i] = st;
    cursor[i]  = st;
    if (i == NND - 1) row_ptr[NND] = inc;
}

__global__ void k_fill(const int* __restrict__ src, const int* __restrict__ dst) {
    int t = blockIdx.x * blockDim.x + threadIdx.x;
    if (t * 4 >= NE) return;
    int4 s = *(const int4*)(src + t * 4);
    int4 d = *(const int4*)(dst + t * 4);
    csr_src[atomicAdd(&cursor[d.x], 1)] = s.x;
    csr_src[atomicAdd(&cursor[d.y], 1)] = s.y;
    csr_src[atomicAdd(&cursor[d.z], 1)] = s.z;
    csr_src[atomicAdd(&cursor[d.w], 1)] = s.w;
}

// ---------------- weight prep: W2->fp16 + fused head weight/bias ----------------

__global__ __launch_bounds__(256) void k_wprep(const float* __restrict__ W2,
                                               const float* __restrict__ Wp1,
                                               const float* __restrict__ bp1,
                                               const float* __restrict__ Wp2,
                                               const float* __restrict__ bp2)
{
    int i = blockIdx.x * blockDim.x + threadIdx.x;
    if (i < D * D) {
        W2h_buf[i] = __float2half_rn(W2[i]);
        return;
    }
    int j = i - D * D;
    if (j >= D * 64) return;
    int k = j >> 6, n = j & 63;
    float s = 0.0f;
#pragma unroll 8
    for (int t = 0; t < D; t++)
        s = fmaf(Wp1[k * D + t], Wp2[t * 64 + n], s);
    Wfh_buf[j] = __float2half_rn(s);
    if (k == 0) {
        float b = bp2[n];
#pragma unroll 8
        for (int t = 0; t < D; t++)
            b = fmaf(bp1[t], Wp2[t * 64 + n], b);
        bF_buf[n] = b;
    }
}

// ---------------- HMMA GEMM (full-K resident): C = A[128rows,128] @ W[128,BN] --------
// 256 threads = 8 warps; warp w owns rows [w*16, w*16+16); mma.sync m16n8k16 fp16->fp32.
// EPI 0: Cq = e4m3(acc * dis[row] * MSCALE)  (fp8 message write)
// EPI 2: Cf = log_softmax(acc + biasC) over row (BN=64)

template <int BN, bool A_HALF, bool W_HALF, int EPI>
__global__ __launch_bounds__(256)
void hgemm(const void* __restrict__ Ain,
           const void* __restrict__ Win,
           const float* __restrict__ biasC,
           const float* __restrict__ dis,
           unsigned char* __restrict__ Cq,
           float* __restrict__ Cf)
{
    constexpr int SAH = D + 8;
    constexpr int SBH = BN + 8;
    constexpr int NT  = BN / 8;
    extern __shared__ __align__(16) __half smem[];
    __half* As = smem;
    __half* Ws = smem + 128 * SAH;

    const int tid  = threadIdx.x;
    const int wid  = tid >> 5;
    const int lane = tid & 31;
    const int row0 = blockIdx.x * 128;
    const int wr0  = wid * 16;

    const uint32_t as_base = (uint32_t)__cvta_generic_to_shared(As);
    const uint32_t ws_base = (uint32_t)__cvta_generic_to_shared(Ws);

    // ---- stage A ----
    if (A_HALF) {
        const __half* Ah = (const __half*)Ain;
#pragma unroll
        for (int p = 0; p < 8; p++) {
            int i  = tid + p * 256;
            int r  = i >> 4, c8 = i & 15;
            int row = row0 + r;
            uint32_t saddr = as_base + (r * SAH + c8 * 8) * 2;
            const __half* gaddr = Ah + (row < NND ? row : 0) * D + c8 * 8;
            cp_async16(saddr, gaddr, row < NND ? 16 : 0);
        }
    } else {
        const float* Af = (const float*)Ain;
#pragma unroll
        for (int p = 0; p < 16; p++) {
            int i  = tid + p * 256;
            int r  = i >> 5, c4 = i & 31;
            int row = row0 + r;
            float4 v = make_float4(0.f, 0.f, 0.f, 0.f);
            if (row < NND)
                v = *(const float4*)(Af + row * D + c4 * 4);
            __half2 h01 = __floats2half2_rn(v.x, v.y);
            __half2 h23 = __floats2half2_rn(v.z, v.w);
            uint2 u;
            u.x = *(uint32_t*)&h01;
            u.y = *(uint32_t*)&h23;
            *(uint2*)(As + r * SAH + c4 * 4) = u;
        }
    }
    // ---- stage W ----
    if (W_HALF) {
        const __half* Wh = (const __half*)Win;
#pragma unroll
        for (int p = 0; p < (D * BN / 8) / 256; p++) {
            int i = tid + p * 256;
            int r = i / (BN / 8), c8 = i % (BN / 8);
            cp_async16(ws_base + (r * SBH + c8 * 8) * 2, Wh + r * BN + c8 * 8, 16);
        }
        cp_async_commit_wait();
    } else {
        const float* Wf = (const float*)Win;
#pragma unroll
        for (int p = 0; p < (D * BN / 4) / 256; p++) {
            int i = tid + p * 256;
            int r = i / (BN / 4), c4 = i % (BN / 4);
            float4 v = *(const float4*)(Wf + r * BN + c4 * 4);
            __half2 h01 = __floats2half2_rn(v.x, v.y);
            __half2 h23 = __floats2half2_rn(v.z, v.w);
            uint2 u;
            u.x = *(uint32_t*)&h01;
            u.y = *(uint32_t*)&h23;
            *(uint2*)(Ws + r * SBH + c4 * 4) = u;
        }
        if (A_HALF) cp_async_commit_wait();
    }
    __syncthreads();

    float c[NT][4];
#pragma unroll
    for (int j = 0; j < NT; j++)
#pragma unroll
        for (int q = 0; q < 4; q++) c[j][q] = 0.0f;

    const uint32_t a_lane = ((wr0 + (lane & 15)) * SAH + (lane >> 4) * 8) * 2;
    const uint32_t b_lane_row = (lane & 15);
    const uint32_t b_lane_col = ((lane & 16) >> 1);

#pragma unroll
    for (int kk = 0; kk < D; kk += 16) {
        uint32_t a0, a1, a2, a3;
        uint32_t aaddr = as_base + a_lane + kk * 2;
        asm volatile("ldmatrix.sync.aligned.m8n8.x4.shared.b16 {%0,%1,%2,%3}, [%4];"
                     : "=r"(a0), "=r"(a1), "=r"(a2), "=r"(a3) : "r"(aaddr));
#pragma unroll
        for (int jt = 0; jt < NT / 2; jt++) {
            uint32_t b0, b1, b2, b3;
            uint32_t baddr = ws_base +
                ((kk + b_lane_row) * SBH + jt * 16 + b_lane_col) * 2;
            asm volatile("ldmatrix.sync.aligned.m8n8.x4.trans.shared.b16 {%0,%1,%2,%3}, [%4];"
                         : "=r"(b0), "=r"(b1), "=r"(b2), "=r"(b3) : "r"(baddr));
            asm volatile("mma.sync.aligned.m16n8k16.row.col.f32.f16.f16.f32 "
                         "{%0,%1,%2,%3},{%4,%5,%6,%7},{%8,%9},{%0,%1,%2,%3};"
                         : "+f"(c[2*jt][0]), "+f"(c[2*jt][1]),
                           "+f"(c[2*jt][2]), "+f"(c[2*jt][3])
                         : "r"(a0), "r"(a1), "r"(a2), "r"(a3), "r"(b0), "r"(b1));
            asm volatile("mma.sync.aligned.m16n8k16.row.col.f32.f16.f16.f32 "
                         "{%0,%1,%2,%3},{%4,%5,%6,%7},{%8,%9},{%0,%1,%2,%3};"
                         : "+f"(c[2*jt+1][0]), "+f"(c[2*jt+1][1]),
                           "+f"(c[2*jt+1][2]), "+f"(c[2*jt+1][3])
                         : "r"(a0), "r"(a1), "r"(a2), "r"(a3), "r"(b2), "r"(b3));
        }
    }

    const int r1 = row0 + wr0 + (lane >> 2);
    const int r2 = r1 + 8;

    if (EPI == 0) {
        float s1 = (r1 < NND) ? dis[r1] * MSCALE : 0.f;
        float s2 = (r2 < NND) ? dis[r2] * MSCALE : 0.f;
#pragma unroll
        for (int j = 0; j < NT; j++) {
            int col = j * 8 + (lane & 3) * 2;
            if (r1 < NND)
                *(unsigned short*)(Cq + r1 * BN + col) =
                    enc_e4m3x2(c[j][0] * s1, c[j][1] * s1);
            if (r2 < NND)
                *(unsigned short*)(Cq + r2 * BN + col) =
                    enc_e4m3x2(c[j][2] * s2, c[j][3] * s2);
        }
    } else {  // EPI 2: BN=64, NT=8, log_softmax per row
        float t[NT][4];
        float m1 = -1e30f, m2 = -1e30f;
#pragma unroll
        for (int j = 0; j < NT; j++) {
            float2 b = *(const float2*)(biasC + j * 8 + (lane & 3) * 2);
            t[j][0] = c[j][0] + b.x; t[j][1] = c[j][1] + b.y;
            t[j][2] = c[j][2] + b.x; t[j][3] = c[j][3] + b.y;
            m1 = fmaxf(m1, fmaxf(t[j][0], t[j][1]));
            m2 = fmaxf(m2, fmaxf(t[j][2], t[j][3]));
        }
#pragma unroll
        for (int o = 1; o <= 2; o <<= 1) {
            m1 = fmaxf(m1, __shfl_xor_sync(0xFFFFFFFFu, m1, o));
            m2 = fmaxf(m2, __shfl_xor_sync(0xFFFFFFFFu, m2, o));
        }
        float s1 = 0.f, s2 = 0.f;
#pragma unroll
        for (int j = 0; j < NT; j++) {
            s1 += expf(t[j][0] - m1) + expf(t[j][1] - m1);
            s2 += expf(t[j][2] - m2) + expf(t[j][3] - m2);
        }
#pragma unroll
        for (int o = 1; o <= 2; o <<= 1) {
            s1 += __shfl_xor_sync(0xFFFFFFFFu, s1, o);
            s2 += __shfl_xor_sync(0xFFFFFFFFu, s2, o);
        }
        float l1 = m1 + logf(s1);
        float l2 = m2 + logf(s2);
#pragma unroll
        for (int j = 0; j < NT; j++) {
            int col = j * 8 + (lane & 3) * 2;
            if (r1 < NND) {
                float2 r; r.x = t[j][0] - l1; r.y = t[j][1] - l1;
                *(float2*)(Cf + r1 * BN + col) = r;
            }
            if (r2 < NND) {
                float2 r; r.x = t[j][2] - l2; r.y = t[j][3] - l2;
                *(float2*)(Cf + r2 * BN + col) = r;
            }
        }
    }
}

// ---------------- CSR gather (fp8 pre-scaled messages, fp16 accum) + finalize -------
// 8-deep scalar-index batches (the measured sweet spot; 16-deep regressed via
// cross-CTA L1tex-queue contention).  h[v] = half(relu(dis[v]/16 * acc + bias))

__device__ __forceinline__ void acc_u32(__half2& a0, __half2& a1, uint32_t u) {
    a0 = __hadd2(a0, dec_e4m3x2((unsigned short)u));
    a1 = __hadd2(a1, dec_e4m3x2((unsigned short)(u >> 16)));
}

__global__ __launch_bounds__(256)
void k_gather_fin(const unsigned char* __restrict__ g, const float* __restrict__ dis,
                  const float* __restrict__ bias, __half* __restrict__ h)
{
    int node = (blockIdx.x * blockDim.x + threadIdx.x) >> 5;
    int lane = threadIdx.x & 31;
    if (node >= NND) return;
    int beg = row_ptr[node];
    int end = row_ptr[node + 1];
    const uint32_t* gp = (const uint32_t*)g;   // 4 fp8 per lane

    __half2 acc0 = __float2half2_rn(0.f);
    __half2 acc1 = __float2half2_rn(0.f);
    acc_u32(acc0, acc1, gp[node * 32 + lane]);   // self-loop message

    int e = beg;
    for (; e + 8 <= end; e += 8) {
        int s0 = __ldg(&csr_src[e + 0]);
        int s1 = __ldg(&csr_src[e + 1]);
        int s2 = __ldg(&csr_src[e + 2]);
        int s3 = __ldg(&csr_src[e + 3]);
        int s4 = __ldg(&csr_src[e + 4]);
        int s5 = __ldg(&csr_src[e + 5]);
        int s6 = __ldg(&csr_src[e + 6]);
        int s7 = __ldg(&csr_src[e + 7]);
        uint32_t u0 = gp[s0 * 32 + lane];
        uint32_t u1 = gp[s1 * 32 + lane];
        uint32_t u2 = gp[s2 * 32 + lane];
        uint32_t u3 = gp[s3 * 32 + lane];
        uint32_t u4 = gp[s4 * 32 + lane];
        uint32_t u5 = gp[s5 * 32 + lane];
        uint32_t u6 = gp[s6 * 32 + lane];
        uint32_t u7 = gp[s7 * 32 + lane];
        acc_u32(acc0, acc1, u0); acc_u32(acc0, acc1, u1);
        acc_u32(acc0, acc1, u2); acc_u32(acc0, acc1, u3);
        acc_u32(acc0, acc1, u4); acc_u32(acc0, acc1, u5);
        acc_u32(acc0, acc1, u6); acc_u32(acc0, acc1, u7);
    }
    for (; e < end; e++)
        acc_u32(acc0, acc1, gp[__ldg(&csr_src[e]) * 32 + lane]);

    float sc = dis[node] * INV_MSCALE;
    float2 f0 = __half22float2(acc0);
    float2 f1 = __half22float2(acc1);
    float4 b = ((const float4*)bias)[lane];
    __half2 r0 = __floats2half2_rn(fmaxf(fmaf(f0.x, sc, b.x), 0.f),
                                   fmaxf(fmaf(f0.y, sc, b.y), 0.f));
    __half2 r1 = __floats2half2_rn(fmaxf(fmaf(f1.x, sc, b.z), 0.f),
                                   fmaxf(fmaf(f1.y, sc, b.w), 0.f));
    uint2 u;
    u.x = *(uint32_t*)&r0;
    u.y = *(uint32_t*)&r1;
    ((uint2*)h)[node * 32 + lane] = u;
}

// ---------------- launch ----------------

extern "C" void kernel_launch(void* const* d_in, const int* in_sizes, int n_in,
                              void* d_out, int out_size)
{
    const float* x   = (const float*)d_in[0];
    const int*   ei  = (const int*)d_in[1];
    const int*   src = ei;
    const int*   dst = ei + NE;
    const float* W1  = (const float*)d_in[2];
    const float* b1  = (const float*)d_in[3];
    const float* W2  = (const float*)d_in[4];
    const float* b2  = (const float*)d_in[5];
    const float* Wp1 = (const float*)d_in[6];
    const float* bp1 = (const float*)d_in[7];
    const float* Wp2 = (const float*)d_in[8];
    const float* bp2 = (const float*)d_in[9];
    float* out = (float*)d_out;

    unsigned char *g_p, *g2_p;
    __half *h_p, *w2h_p, *wfh_p;
    float *dis_p, *bf_p;
    int *deg_p;
    cudaGetSymbolAddress((void**)&g_p,   g_buf);
    cudaGetSymbolAddress((void**)&g2_p,  g2_buf);
    cudaGetSymbolAddress((void**)&h_p,   h_buf);
    cudaGetSymbolAddress((void**)&dis_p, dis_buf);
    cudaGetSymbolAddress((void**)&w2h_p, W2h_buf);
    cudaGetSymbolAddress((void**)&wfh_p, Wfh_buf);
    cudaGetSymbolAddress((void**)&bf_p,  bF_buf);
    cudaGetSymbolAddress((void**)&deg_p, deg_buf);

    const int SM_BN128 = (128 * (D + 8) + D * (128 + 8)) * 2;  // 69632
    const int SM_BN64  = (128 * (D + 8) + D * (64 + 8))  * 2;  // 53248

    static cudaStream_t s2 = nullptr;
    static cudaEvent_t ev_fork, ev_dis, ev_csr, ev_w;
    if (!s2) {
        cudaStreamCreateWithFlags(&s2, cudaStreamNonBlocking);
        cudaEventCreateWithFlags(&ev_fork, cudaEventDisableTiming);
        cudaEventCreateWithFlags(&ev_dis,  cudaEventDisableTiming);
        cudaEventCreateWithFlags(&ev_csr,  cudaEventDisableTiming);
        cudaEventCreateWithFlags(&ev_w,    cudaEventDisableTiming);
        cudaFuncSetAttribute((const void*)hgemm<128, false, false, 0>,
                             cudaFuncAttributeMaxDynamicSharedMemorySize, SM_BN128);
        cudaFuncSetAttribute((const void*)hgemm<128, true, true, 0>,
                             cudaFuncAttributeMaxDynamicSharedMemorySize, SM_BN128);
        cudaFuncSetAttribute((const void*)hgemm<64, true, true, 2>,
                             cudaFuncAttributeMaxDynamicSharedMemorySize, SM_BN64);
    }

    const int GEMM_BLOCKS   = (NND + 127) / 128;       // 782
    const int GATHER_BLOCKS = (NND * 32 + 255) / 256;  // 12500
    const int EDGE4_BLOCKS  = (NE / 4 + 255) / 256;    // 1563

    // ---- fork: CSR build first on s2 (critical), then weight prep ----
    cudaEventRecord(ev_fork, 0);
    cudaStreamWaitEvent(s2, ev_fork, 0);

    cudaMemsetAsync(deg_p, 0, NND * sizeof(int), s2);
    k_count_deg<<<EDGE4_BLOCKS, 256, 0, s2>>>(dst);
    k_scan1<<<SCAN_BLOCKS, SCB, 0, s2>>>();     // also writes dis
    cudaEventRecord(ev_dis, s2);
    k_scan3<<<SCAN_BLOCKS, SCB, 0, s2>>>();     // self-computed block offsets
    k_fill<<<EDGE4_BLOCKS, 256, 0, s2>>>(src, dst);
    cudaEventRecord(ev_csr, s2);
    k_wprep<<<(D * D + D * 64 + 255) / 256, 256, 0, s2>>>(W2, Wp1, bp1, Wp2, bp2);
    cudaEventRecord(ev_w, s2);

    // main: GEMM1 (fp32 A + fp32 W converted in-staging): g = e4m3((x@W1)*dis*16)
    cudaStreamWaitEvent(0, ev_dis, 0);
    hgemm<128, false, false, 0><<<GEMM_BLOCKS, 256, SM_BN128>>>(
        x, W1, nullptr, dis_p, g_p, nullptr);

    cudaStreamWaitEvent(0, ev_csr, 0);

    // ---- layer 1 aggregate: h = half(relu(dis/16*gather(g) + b1)) ----
    k_gather_fin<<<GATHER_BLOCKS, 256>>>(g_p, dis_p, b1, h_p);

    cudaStreamWaitEvent(0, ev_w, 0);

    // ---- layer 2: g2 = e4m3((h@W2)*dis*16) ; h = half(relu(dis/16*gather(g2) + b2)) ----
    hgemm<128, true, true, 0><<<GEMM_BLOCKS, 256, SM_BN128>>>(
        h_p, w2h_p, nullptr, dis_p, g2_p, nullptr);
    k_gather_fin<<<GATHER_BLOCKS, 256>>>(g2_p, dis_p, b2, h_p);

    // ---- fused head + log_softmax: out = logsoftmax(h @ Wf + bF) ----
    hgemm<64, true, true, 2><<<GEMM_BLOCKS, 256, SM_BN64>>>(
        h_p, wfh_p, bf_p, dis_p, nullptr, out);
}